// round 1
// baseline (speedup 1.0000x reference)
#include <cuda_runtime.h>

// Problem constants
// B=32, N=512, C=1024, H=16, HD=64, SCALE=0.125

// Scratch: qkv [3][B][H][N][HD] and attention output [B][N][C]
__device__ float g_qkv[3ull * 32 * 16 * 512 * 64];   // 192 MB
__device__ float g_ao [32ull * 512 * 1024];          // 64 MB

// ---------------------------------------------------------------------------
// SGEMM building block: C[m,n] = sum_k A[m,k] * W[n,k]  (both row-major, NT)
// 128x128 tile, BK=16, 256 threads, 8x8 per-thread microtile.
// ---------------------------------------------------------------------------
#define BM 128
#define BN 128
#define BKK 16

// GEMM 1: x[16384,1024] @ W_qkv[3072,1024]^T, epilogue scatters into g_qkv
// with Q scaled by 0.125.
__global__ __launch_bounds__(256)
void qkv_gemm(const float* __restrict__ A, const float* __restrict__ W)
{
    const int K = 1024;
    __shared__ float As[BKK][BM];
    __shared__ float Bs[BKK][BN];
    const int tid = threadIdx.x;
    const int tx = tid & 15;
    const int ty = tid >> 4;
    const int rowBase = blockIdx.y * BM;
    const int colBase = blockIdx.x * BN;

    float acc[8][8];
    #pragma unroll
    for (int i = 0; i < 8; i++)
        #pragma unroll
        for (int j = 0; j < 8; j++) acc[i][j] = 0.f;

    for (int k0 = 0; k0 < K; k0 += BKK) {
        #pragma unroll
        for (int i = 0; i < 2; i++) {
            int idx = tid + i * 256;       // 0..511
            int r   = idx >> 2;            // 0..127
            int c4  = idx & 3;             // 0..3
            float4 va = *(const float4*)(A + (size_t)(rowBase + r) * K + k0 + c4 * 4);
            As[c4*4+0][r] = va.x; As[c4*4+1][r] = va.y;
            As[c4*4+2][r] = va.z; As[c4*4+3][r] = va.w;
            float4 vb = *(const float4*)(W + (size_t)(colBase + r) * K + k0 + c4 * 4);
            Bs[c4*4+0][r] = vb.x; Bs[c4*4+1][r] = vb.y;
            Bs[c4*4+2][r] = vb.z; Bs[c4*4+3][r] = vb.w;
        }
        __syncthreads();
        #pragma unroll
        for (int kk = 0; kk < BKK; kk++) {
            float ar[8], br[8];
            #pragma unroll
            for (int i = 0; i < 8; i++) ar[i] = As[kk][ty * 8 + i];
            #pragma unroll
            for (int j = 0; j < 8; j++) br[j] = Bs[kk][tx * 8 + j];
            #pragma unroll
            for (int i = 0; i < 8; i++)
                #pragma unroll
                for (int j = 0; j < 8; j++)
                    acc[i][j] += ar[i] * br[j];
        }
        __syncthreads();
    }

    // Scatter epilogue into g_qkv[t][b][h][nn][hd], Q scaled.
    #pragma unroll
    for (int i = 0; i < 8; i++) {
        int m  = rowBase + ty * 8 + i;
        int b  = m >> 9;          // /512
        int nn = m & 511;
        #pragma unroll
        for (int j = 0; j < 8; j++) {
            int n   = colBase + tx * 8 + j;
            int t   = n >> 10;        // 0=q,1=k,2=v
            int rem = n & 1023;
            int h   = rem >> 6;
            int hd  = rem & 63;
            float v = acc[i][j];
            if (t == 0) v *= 0.125f;
            g_qkv[((((size_t)t * 32 + b) * 16 + h) * 512 + nn) * 64 + hd] = v;
        }
    }
}

// GEMM 2: g_ao[16384,1024] @ W_proj[1024,1024]^T + b_proj -> out
__global__ __launch_bounds__(256)
void proj_gemm(const float* __restrict__ W, const float* __restrict__ bias,
               float* __restrict__ Cout)
{
    const int K = 1024;
    const int Nc = 1024;
    __shared__ float As[BKK][BM];
    __shared__ float Bs[BKK][BN];
    const int tid = threadIdx.x;
    const int tx = tid & 15;
    const int ty = tid >> 4;
    const int rowBase = blockIdx.y * BM;
    const int colBase = blockIdx.x * BN;
    const float* A = g_ao;

    float acc[8][8];
    #pragma unroll
    for (int i = 0; i < 8; i++)
        #pragma unroll
        for (int j = 0; j < 8; j++) acc[i][j] = 0.f;

    for (int k0 = 0; k0 < K; k0 += BKK) {
        #pragma unroll
        for (int i = 0; i < 2; i++) {
            int idx = tid + i * 256;
            int r   = idx >> 2;
            int c4  = idx & 3;
            float4 va = *(const float4*)(A + (size_t)(rowBase + r) * K + k0 + c4 * 4);
            As[c4*4+0][r] = va.x; As[c4*4+1][r] = va.y;
            As[c4*4+2][r] = va.z; As[c4*4+3][r] = va.w;
            float4 vb = *(const float4*)(W + (size_t)(colBase + r) * K + k0 + c4 * 4);
            Bs[c4*4+0][r] = vb.x; Bs[c4*4+1][r] = vb.y;
            Bs[c4*4+2][r] = vb.z; Bs[c4*4+3][r] = vb.w;
        }
        __syncthreads();
        #pragma unroll
        for (int kk = 0; kk < BKK; kk++) {
            float ar[8], br[8];
            #pragma unroll
            for (int i = 0; i < 8; i++) ar[i] = As[kk][ty * 8 + i];
            #pragma unroll
            for (int j = 0; j < 8; j++) br[j] = Bs[kk][tx * 8 + j];
            #pragma unroll
            for (int i = 0; i < 8; i++)
                #pragma unroll
                for (int j = 0; j < 8; j++)
                    acc[i][j] += ar[i] * br[j];
        }
        __syncthreads();
    }

    #pragma unroll
    for (int i = 0; i < 8; i++) {
        int m = rowBase + ty * 8 + i;
        #pragma unroll
        for (int j = 0; j < 8; j++) {
            int n = colBase + tx * 8 + j;
            Cout[(size_t)m * Nc + n] = acc[i][j] + bias[n];
        }
    }
}

// ---------------------------------------------------------------------------
// Flash attention, fp32. 1 CTA per (b, h, q-block of 128). 1 thread = 1 q row.
// Only the column mask bias matters (row bias cancels in softmax).
// ---------------------------------------------------------------------------
__global__ __launch_bounds__(128)
void attn_kernel(const float* __restrict__ mask)
{
    const int b = blockIdx.z;
    const int h = blockIdx.y;
    const int tid = threadIdx.x;
    const int r = blockIdx.x * 128 + tid;   // q sequence index

    const float* Qp = g_qkv + (((size_t)0 * 32 + b) * 16 + h) * 512 * 64;
    const float* Kp = g_qkv + (((size_t)1 * 32 + b) * 16 + h) * 512 * 64;
    const float* Vp = g_qkv + (((size_t)2 * 32 + b) * 16 + h) * 512 * 64;

    float q[64];
    #pragma unroll
    for (int d4 = 0; d4 < 16; d4++) {
        float4 v = *(const float4*)(Qp + (size_t)r * 64 + d4 * 4);
        q[d4*4+0] = v.x; q[d4*4+1] = v.y; q[d4*4+2] = v.z; q[d4*4+3] = v.w;
    }

    float o[64];
    #pragma unroll
    for (int d = 0; d < 64; d++) o[d] = 0.f;
    float mx = -1e30f, l = 0.f;

    __shared__ float Ks[32][64];
    __shared__ float Vs[32][64];
    __shared__ float Ms[32];

    for (int kt = 0; kt < 512; kt += 32) {
        __syncthreads();
        #pragma unroll
        for (int i = 0; i < 4; i++) {
            int idx = tid + i * 128;     // 0..511
            int jr  = idx >> 4;          // 0..31
            int c4  = idx & 15;          // 0..15
            *(float4*)&Ks[jr][c4 * 4] =
                *(const float4*)(Kp + (size_t)(kt + jr) * 64 + c4 * 4);
            *(float4*)&Vs[jr][c4 * 4] =
                *(const float4*)(Vp + (size_t)(kt + jr) * 64 + c4 * 4);
        }
        if (tid < 32) Ms[tid] = mask[b * 512 + kt + tid];
        __syncthreads();

        float s[32];
        float tmax = -1e30f;
        #pragma unroll
        for (int j = 0; j < 32; j++) {
            float a0 = 0.f, a1 = 0.f, a2 = 0.f, a3 = 0.f;
            #pragma unroll
            for (int d = 0; d < 64; d += 4) {
                a0 += q[d+0] * Ks[j][d+0];
                a1 += q[d+1] * Ks[j][d+1];
                a2 += q[d+2] * Ks[j][d+2];
                a3 += q[d+3] * Ks[j][d+3];
            }
            float sv = (a0 + a1) + (a2 + a3) + Ms[j];
            s[j] = sv;
            tmax = fmaxf(tmax, sv);
        }

        float mnew  = fmaxf(mx, tmax);
        float alpha = __expf(mx - mnew);
        l *= alpha;
        #pragma unroll
        for (int d = 0; d < 64; d++) o[d] *= alpha;

        #pragma unroll
        for (int j = 0; j < 32; j++) {
            float p = __expf(s[j] - mnew);
            l += p;
            #pragma unroll
            for (int d = 0; d < 64; d++) o[d] += p * Vs[j][d];
        }
        mx = mnew;
    }

    float inv = 1.0f / l;
    float* Op = g_ao + ((size_t)b * 512 + r) * 1024 + h * 64;
    #pragma unroll
    for (int d4 = 0; d4 < 16; d4++) {
        float4 v = make_float4(o[d4*4+0] * inv, o[d4*4+1] * inv,
                               o[d4*4+2] * inv, o[d4*4+3] * inv);
        *(float4*)(Op + d4 * 4) = v;
    }
}

// ---------------------------------------------------------------------------
extern "C" void kernel_launch(void* const* d_in, const int* in_sizes, int n_in,
                              void* d_out, int out_size)
{
    const float* x = nullptr;
    const float* mask = nullptr;
    const float* wqkv = nullptr;
    const float* wproj = nullptr;
    const float* bproj = nullptr;

    for (int i = 0; i < n_in; i++) {
        switch (in_sizes[i]) {
            case 32 * 512 * 1024:  x     = (const float*)d_in[i]; break;
            case 32 * 512:         mask  = (const float*)d_in[i]; break;
            case 3 * 1024 * 1024:  wqkv  = (const float*)d_in[i]; break;
            case 1024 * 1024:      wproj = (const float*)d_in[i]; break;
            case 1024:             bproj = (const float*)d_in[i]; break;
            default: break;
        }
    }

    // QKV projection: [16384,1024] x [3072,1024]^T
    qkv_gemm<<<dim3(3072 / BN, 16384 / BM), 256>>>(x, wqkv);
    // Flash attention: (q-tiles=4, H=16, B=32)
    attn_kernel<<<dim3(4, 16, 32), 128>>>(mask);
    // Output projection + bias: [16384,1024] x [1024,1024]^T
    proj_gemm<<<dim3(1024 / BN, 16384 / BM), 256>>>(wproj, bproj, (float*)d_out);
}

// round 3
// speedup vs baseline: 1.8848x; 1.8848x over previous
#include <cuda_runtime.h>
#include <cuda_bf16.h>
#include <cstdint>

// ===========================================================================
// Problem constants: B=32, N=512, C=1024, H=16, HD=64, SCALE=0.125
// NOTE: harness toolchain emits compute_103 PTX (no 'a'), so tcgen05 is
// unavailable. Tensor cores are reached via mma.sync (HMMA) instead.
// ===========================================================================

// fp32 scratch for qkv [3][B][H][N][HD]
__device__ float g_qkv[3ull * 32 * 16 * 512 * 64];
// split-bf16 buffers
__device__ __nv_bfloat16 g_xh[16777216], g_xl[16777216];      // x  [16384,1024]
__device__ __nv_bfloat16 g_wqh[3145728],  g_wql[3145728];     // W_qkv [3072,1024]
__device__ __nv_bfloat16 g_wph[1048576],  g_wpl[1048576];     // W_proj [1024,1024]
__device__ __nv_bfloat16 g_aoh[16777216], g_aol[16777216];    // attn out [B,N,C]

// ---------------------------------------------------------------------------
// PTX helpers (all plain sm_80+ PTX — safe under compute_103)
// ---------------------------------------------------------------------------
__device__ __forceinline__ uint32_t smem_u32(const void* p) {
    uint32_t a;
    asm("{ .reg .u64 t; cvta.to.shared.u64 t, %1; cvt.u32.u64 %0, t; }" : "=r"(a) : "l"(p));
    return a;
}
__device__ __forceinline__ void mma_bf16(float* c, const uint32_t* a, const uint32_t* b) {
    asm volatile(
        "mma.sync.aligned.m16n8k16.row.col.f32.bf16.bf16.f32 "
        "{%0,%1,%2,%3}, {%4,%5,%6,%7}, {%8,%9}, {%0,%1,%2,%3};"
        : "+f"(c[0]), "+f"(c[1]), "+f"(c[2]), "+f"(c[3])
        : "r"(a[0]), "r"(a[1]), "r"(a[2]), "r"(a[3]), "r"(b[0]), "r"(b[1]));
}
__device__ __forceinline__ void ldsm_x4(uint32_t* r, uint32_t addr) {
    asm volatile("ldmatrix.sync.aligned.m8n8.x4.shared.b16 {%0,%1,%2,%3}, [%4];"
        : "=r"(r[0]), "=r"(r[1]), "=r"(r[2]), "=r"(r[3]) : "r"(addr));
}
__device__ __forceinline__ void ldsm_x2(uint32_t* r, uint32_t addr) {
    asm volatile("ldmatrix.sync.aligned.m8n8.x2.shared.b16 {%0,%1}, [%2];"
        : "=r"(r[0]), "=r"(r[1]) : "r"(addr));
}
__device__ __forceinline__ void cp16(uint32_t saddr, const void* g) {
    asm volatile("cp.async.cg.shared.global [%0], [%1], 16;" :: "r"(saddr), "l"(g));
}
#define CP_COMMIT() asm volatile("cp.async.commit_group;" ::: "memory")
#define CP_WAIT1()  asm volatile("cp.async.wait_group 1;" ::: "memory")
#define CP_WAIT0()  asm volatile("cp.async.wait_group 0;" ::: "memory")

// ---------------------------------------------------------------------------
// fp32 -> (hi, lo) bf16 split
// ---------------------------------------------------------------------------
__global__ __launch_bounds__(256)
void cvt_pair(const float* __restrict__ in, __nv_bfloat16* __restrict__ hi,
              __nv_bfloat16* __restrict__ lo, int n4)
{
    int i = blockIdx.x * blockDim.x + threadIdx.x;
    if (i >= n4) return;
    float4 v = ((const float4*)in)[i];
    __nv_bfloat16 h0 = __float2bfloat16(v.x), h1 = __float2bfloat16(v.y);
    __nv_bfloat16 h2 = __float2bfloat16(v.z), h3 = __float2bfloat16(v.w);
    __nv_bfloat162 p0, p1;
    p0.x = h0; p0.y = h1; p1.x = h2; p1.y = h3;
    ((__nv_bfloat162*)hi)[2*i]   = p0;
    ((__nv_bfloat162*)hi)[2*i+1] = p1;
    __nv_bfloat162 q0, q1;
    q0.x = __float2bfloat16(v.x - __bfloat162float(h0));
    q0.y = __float2bfloat16(v.y - __bfloat162float(h1));
    q1.x = __float2bfloat16(v.z - __bfloat162float(h2));
    q1.y = __float2bfloat16(v.w - __bfloat162float(h3));
    ((__nv_bfloat162*)lo)[2*i]   = q0;
    ((__nv_bfloat162*)lo)[2*i+1] = q1;
}

// ---------------------------------------------------------------------------
// HMMA GEMM: C[m,n] = sum_k A[m,k]*B[n,k], bf16 split (hi+lo, 3 MMA passes),
// fp32 accum. K=1024. CTA tile 128x128, BK=32, 8 warps (2m x 4n), 64x32/warp.
// mode 0: scatter into g_qkv (Q scaled). mode 1: +bias -> Cout.
// ---------------------------------------------------------------------------
#define PK 40                       // padded K halves per row (32 + 8)
#define MATB (128 * PK * 2)         // one 128x32 tile, padded: 10240 B
#define BUFB (4 * MATB)             // Ah, Al, Bh, Bl: 40960 B
#define GSMEM (2 * BUFB)            // double buffered: 81920 B
#define NCHUNK 32

__global__ __launch_bounds__(256)
void hmma_gemm(const __nv_bfloat16* __restrict__ Ah, const __nv_bfloat16* __restrict__ Al,
               const __nv_bfloat16* __restrict__ Bh, const __nv_bfloat16* __restrict__ Bl,
               const float* __restrict__ bias, float* __restrict__ Cout, int mode)
{
    extern __shared__ char smem[];
    const uint32_t sb = smem_u32(smem);
    const int tid  = threadIdx.x;
    const int wid  = tid >> 5, lane = tid & 31;
    const int wm   = wid >> 2, wn = wid & 3;         // 2 x 4 warp grid
    const int rowBase = blockIdx.y * 128;
    const int colBase = blockIdx.x * 128;

    const __nv_bfloat16* gp[4] = {Ah, Al, Bh, Bl};

    // Load one K-chunk (4 tiles of 128x32 bf16) into buffer `buf`.
    auto load_chunk = [&](int ci, int buf) {
        const int k0 = ci * 32;
        #pragma unroll
        for (int a = 0; a < 4; a++) {
            const __nv_bfloat16* src = gp[a];
            const int gRow = (a < 2) ? rowBase : colBase;
            const uint32_t mbase = sb + buf * BUFB + a * MATB;
            #pragma unroll
            for (int it = 0; it < 2; it++) {
                int idx = it * 256 + tid;        // 0..511
                int row = idx >> 2;              // 0..127
                int seg = idx & 3;               // 0..3 (8 halves each)
                cp16(mbase + (uint32_t)(row * PK + seg * 8) * 2,
                     src + (size_t)(gRow + row) * 1024 + k0 + seg * 8);
            }
        }
        CP_COMMIT();
    };

    float acc[4][4][4];
    #pragma unroll
    for (int mi = 0; mi < 4; mi++)
        #pragma unroll
        for (int ni = 0; ni < 4; ni++)
            #pragma unroll
            for (int j = 0; j < 4; j++) acc[mi][ni][j] = 0.f;

    load_chunk(0, 0);

    for (int ci = 0; ci < NCHUNK; ci++) {
        const int buf = ci & 1;
        if (ci + 1 < NCHUNK) { load_chunk(ci + 1, buf ^ 1); CP_WAIT1(); }
        else                 { CP_WAIT0(); }
        __syncthreads();

        const uint32_t aBase = sb + buf * BUFB;            // Ah
        const uint32_t bBase = sb + buf * BUFB + 2 * MATB; // Bh

        #pragma unroll
        for (int ks = 0; ks < 2; ks++) {
            uint32_t ah[4][4], al[4][4], bh[4][2], bl[4][2];
            const int acol = ks * 16 + (lane >> 4) * 8;
            const int bcol = ks * 16 + ((lane >> 3) & 1) * 8;
            #pragma unroll
            for (int mi = 0; mi < 4; mi++) {
                int r = wm * 64 + mi * 16 + (lane & 15);
                ldsm_x4(ah[mi], aBase + (uint32_t)(r * PK + acol) * 2);
                ldsm_x4(al[mi], aBase + MATB + (uint32_t)(r * PK + acol) * 2);
            }
            #pragma unroll
            for (int ni = 0; ni < 4; ni++) {
                int rn = wn * 32 + ni * 8 + (lane & 7);
                ldsm_x2(bh[ni], bBase + (uint32_t)(rn * PK + bcol) * 2);
                ldsm_x2(bl[ni], bBase + MATB + (uint32_t)(rn * PK + bcol) * 2);
            }
            #pragma unroll
            for (int mi = 0; mi < 4; mi++)
                #pragma unroll
                for (int ni = 0; ni < 4; ni++) {
                    mma_bf16(acc[mi][ni], ah[mi], bh[ni]);
                    mma_bf16(acc[mi][ni], ah[mi], bl[ni]);
                    mma_bf16(acc[mi][ni], al[mi], bh[ni]);
                }
        }
        __syncthreads();
    }

    // Epilogue. C fragment: (c0,c1) at row lane/4, cols 2*(lane%4)+{0,1};
    // (c2,c3) at row+8.
    const int rBase = rowBase + wm * 64 + (lane >> 2);
    const int cBase = colBase + wn * 32 + (lane & 3) * 2;
    #pragma unroll
    for (int mi = 0; mi < 4; mi++) {
        #pragma unroll
        for (int half = 0; half < 2; half++) {
            const int m = rBase + mi * 16 + half * 8;
            #pragma unroll
            for (int ni = 0; ni < 4; ni++) {
                const int n = cBase + ni * 8;
                const float c0 = acc[mi][ni][half * 2 + 0];
                const float c1 = acc[mi][ni][half * 2 + 1];
                if (mode == 0) {
                    int t = n >> 10, rem = n & 1023, h = rem >> 6, hd = rem & 63;
                    int b = m >> 9, nn = m & 511;
                    float s = (t == 0) ? 0.125f : 1.0f;
                    float* dst = g_qkv + ((((size_t)t * 32 + b) * 16 + h) * 512 + nn) * 64 + hd;
                    *(float2*)dst = make_float2(c0 * s, c1 * s);
                } else {
                    float* dst = Cout + (size_t)m * 1024 + n;
                    *(float2*)dst = make_float2(c0 + bias[n], c1 + bias[n + 1]);
                }
            }
        }
    }
}

// ---------------------------------------------------------------------------
// Flash attention, fp32. 1 CTA per (b, h, q-block of 128). 1 thread = 1 q row.
// Row mask bias cancels in softmax; only column bias applied. Emits split
// bf16 (hi, lo) for the proj GEMM.
// ---------------------------------------------------------------------------
__global__ __launch_bounds__(128)
void attn_kernel(const float* __restrict__ mask)
{
    const int b = blockIdx.z;
    const int h = blockIdx.y;
    const int tid = threadIdx.x;
    const int r = blockIdx.x * 128 + tid;

    const float* Qp = g_qkv + (((size_t)0 * 32 + b) * 16 + h) * 512 * 64;
    const float* Kp = g_qkv + (((size_t)1 * 32 + b) * 16 + h) * 512 * 64;
    const float* Vp = g_qkv + (((size_t)2 * 32 + b) * 16 + h) * 512 * 64;

    float q[64];
    #pragma unroll
    for (int d4 = 0; d4 < 16; d4++) {
        float4 v = *(const float4*)(Qp + (size_t)r * 64 + d4 * 4);
        q[d4*4+0] = v.x; q[d4*4+1] = v.y; q[d4*4+2] = v.z; q[d4*4+3] = v.w;
    }

    float o[64];
    #pragma unroll
    for (int d = 0; d < 64; d++) o[d] = 0.f;
    float mx = -1e30f, l = 0.f;

    __shared__ float Ks[32][64];
    __shared__ float Vs[32][64];
    __shared__ float Ms[32];

    for (int kt = 0; kt < 512; kt += 32) {
        __syncthreads();
        #pragma unroll
        for (int i = 0; i < 4; i++) {
            int idx = tid + i * 128;
            int jr  = idx >> 4;
            int c4  = idx & 15;
            *(float4*)&Ks[jr][c4 * 4] =
                *(const float4*)(Kp + (size_t)(kt + jr) * 64 + c4 * 4);
            *(float4*)&Vs[jr][c4 * 4] =
                *(const float4*)(Vp + (size_t)(kt + jr) * 64 + c4 * 4);
        }
        if (tid < 32) Ms[tid] = mask[b * 512 + kt + tid];
        __syncthreads();

        float s[32];
        float tmax = -1e30f;
        #pragma unroll
        for (int j = 0; j < 32; j++) {
            float a0 = 0.f, a1 = 0.f, a2 = 0.f, a3 = 0.f;
            #pragma unroll
            for (int d = 0; d < 64; d += 4) {
                a0 += q[d+0] * Ks[j][d+0];
                a1 += q[d+1] * Ks[j][d+1];
                a2 += q[d+2] * Ks[j][d+2];
                a3 += q[d+3] * Ks[j][d+3];
            }
            float sv = (a0 + a1) + (a2 + a3) + Ms[j];
            s[j] = sv;
            tmax = fmaxf(tmax, sv);
        }

        float mnew  = fmaxf(mx, tmax);
        float alpha = __expf(mx - mnew);
        l *= alpha;
        #pragma unroll
        for (int d = 0; d < 64; d++) o[d] *= alpha;

        #pragma unroll
        for (int j = 0; j < 32; j++) {
            float p = __expf(s[j] - mnew);
            l += p;
            #pragma unroll
            for (int d = 0; d < 64; d++) o[d] += p * Vs[j][d];
        }
        mx = mnew;
    }

    const float inv = 1.0f / l;
    const size_t base = ((size_t)b * 512 + r) * 1024 + h * 64;
    #pragma unroll
    for (int d = 0; d < 64; d += 2) {
        float v0 = o[d] * inv, v1 = o[d+1] * inv;
        __nv_bfloat16 h0 = __float2bfloat16(v0), h1 = __float2bfloat16(v1);
        __nv_bfloat162 ph2; ph2.x = h0; ph2.y = h1;
        *(__nv_bfloat162*)(g_aoh + base + d) = ph2;
        __nv_bfloat162 pl2;
        pl2.x = __float2bfloat16(v0 - __bfloat162float(h0));
        pl2.y = __float2bfloat16(v1 - __bfloat162float(h1));
        *(__nv_bfloat162*)(g_aol + base + d) = pl2;
    }
}

// ---------------------------------------------------------------------------
extern "C" void kernel_launch(void* const* d_in, const int* in_sizes, int n_in,
                              void* d_out, int out_size)
{
    const float* x = nullptr;
    const float* mask = nullptr;
    const float* wqkv = nullptr;
    const float* wproj = nullptr;
    const float* bproj = nullptr;

    for (int i = 0; i < n_in; i++) {
        switch (in_sizes[i]) {
            case 32 * 512 * 1024:  x     = (const float*)d_in[i]; break;
            case 32 * 512:         mask  = (const float*)d_in[i]; break;
            case 3 * 1024 * 1024:  wqkv  = (const float*)d_in[i]; break;
            case 1024 * 1024:      wproj = (const float*)d_in[i]; break;
            case 1024:             bproj = (const float*)d_in[i]; break;
            default: break;
        }
    }

    static bool attr_set = false;
    if (!attr_set) {
        cudaFuncSetAttribute(hmma_gemm, cudaFuncAttributeMaxDynamicSharedMemorySize, GSMEM);
        attr_set = true;
    }

    __nv_bfloat16 *xh, *xl, *wqh, *wql, *wph, *wpl, *aoh, *aol;
    cudaGetSymbolAddress((void**)&xh,  g_xh);
    cudaGetSymbolAddress((void**)&xl,  g_xl);
    cudaGetSymbolAddress((void**)&wqh, g_wqh);
    cudaGetSymbolAddress((void**)&wql, g_wql);
    cudaGetSymbolAddress((void**)&wph, g_wph);
    cudaGetSymbolAddress((void**)&wpl, g_wpl);
    cudaGetSymbolAddress((void**)&aoh, g_aoh);
    cudaGetSymbolAddress((void**)&aol, g_aol);

    // split fp32 -> (hi, lo) bf16
    cvt_pair<<<(4194304 + 255) / 256, 256>>>(x,     xh,  xl,  4194304);
    cvt_pair<<<(786432  + 255) / 256, 256>>>(wqkv,  wqh, wql, 786432);
    cvt_pair<<<(262144  + 255) / 256, 256>>>(wproj, wph, wpl, 262144);

    // QKV projection: [16384,1024] x [3072,1024]^T -> g_qkv (HMMA)
    hmma_gemm<<<dim3(24, 128), 256, GSMEM>>>(xh, xl, wqh, wql, nullptr, nullptr, 0);
    // Flash attention -> g_aoh/g_aol (split bf16)
    attn_kernel<<<dim3(4, 16, 32), 128>>>(mask);
    // Output projection + bias: [16384,1024] x [1024,1024]^T -> d_out (HMMA)
    hmma_gemm<<<dim3(8, 128), 256, GSMEM>>>(aoh, aol, wph, wpl, bproj, (float*)d_out, 1);
}

// round 4
// speedup vs baseline: 2.9356x; 1.5575x over previous
#include <cuda_runtime.h>
#include <cuda_bf16.h>
#include <cstdint>

// ===========================================================================
// Problem constants: B=32, N=512, C=1024, H=16, HD=64, SCALE=0.125
// compute_103 toolchain: no tcgen05; tensor cores via mma.sync (HMMA).
// ===========================================================================

// split-bf16 qkv [3][B][H][N][HD] (Q pre-scaled by 0.125)
__device__ __nv_bfloat16 g_qkvh[3ull * 32 * 16 * 512 * 64];
__device__ __nv_bfloat16 g_qkvl[3ull * 32 * 16 * 512 * 64];
// split-bf16 inputs
__device__ __nv_bfloat16 g_xh[16777216], g_xl[16777216];      // x  [16384,1024]
__device__ __nv_bfloat16 g_wqh[3145728],  g_wql[3145728];     // W_qkv [3072,1024]
__device__ __nv_bfloat16 g_wph[1048576],  g_wpl[1048576];     // W_proj [1024,1024]
__device__ __nv_bfloat16 g_aoh[16777216], g_aol[16777216];    // attn out [B,N,C]

// ---------------------------------------------------------------------------
// PTX helpers (plain sm_80+ PTX — safe under compute_103)
// ---------------------------------------------------------------------------
__device__ __forceinline__ uint32_t smem_u32(const void* p) {
    uint32_t a;
    asm("{ .reg .u64 t; cvta.to.shared.u64 t, %1; cvt.u32.u64 %0, t; }" : "=r"(a) : "l"(p));
    return a;
}
__device__ __forceinline__ void mma_bf16(float* c, const uint32_t* a, const uint32_t* b) {
    asm volatile(
        "mma.sync.aligned.m16n8k16.row.col.f32.bf16.bf16.f32 "
        "{%0,%1,%2,%3}, {%4,%5,%6,%7}, {%8,%9}, {%0,%1,%2,%3};"
        : "+f"(c[0]), "+f"(c[1]), "+f"(c[2]), "+f"(c[3])
        : "r"(a[0]), "r"(a[1]), "r"(a[2]), "r"(a[3]), "r"(b[0]), "r"(b[1]));
}
__device__ __forceinline__ void ldsm_x4(uint32_t* r, uint32_t addr) {
    asm volatile("ldmatrix.sync.aligned.m8n8.x4.shared.b16 {%0,%1,%2,%3}, [%4];"
        : "=r"(r[0]), "=r"(r[1]), "=r"(r[2]), "=r"(r[3]) : "r"(addr));
}
__device__ __forceinline__ void ldsm_x4_t(uint32_t* r, uint32_t addr) {
    asm volatile("ldmatrix.sync.aligned.m8n8.x4.trans.shared.b16 {%0,%1,%2,%3}, [%4];"
        : "=r"(r[0]), "=r"(r[1]), "=r"(r[2]), "=r"(r[3]) : "r"(addr));
}
__device__ __forceinline__ void ldsm_x2(uint32_t* r, uint32_t addr) {
    asm volatile("ldmatrix.sync.aligned.m8n8.x2.shared.b16 {%0,%1}, [%2];"
        : "=r"(r[0]), "=r"(r[1]) : "r"(addr));
}
__device__ __forceinline__ void cp16(uint32_t saddr, const void* g) {
    asm volatile("cp.async.cg.shared.global [%0], [%1], 16;" :: "r"(saddr), "l"(g));
}
#define CP_COMMIT() asm volatile("cp.async.commit_group;" ::: "memory")
#define CP_WAIT1()  asm volatile("cp.async.wait_group 1;" ::: "memory")
#define CP_WAIT0()  asm volatile("cp.async.wait_group 0;" ::: "memory")

__device__ __forceinline__ uint32_t pack_bf16(float a, float b) {
    __nv_bfloat162 p;
    p.x = __float2bfloat16(a); p.y = __float2bfloat16(b);
    return *(uint32_t*)&p;
}
__device__ __forceinline__ uint32_t pack_bf16_res(float a, float b, uint32_t hipack) {
    __nv_bfloat162 hp = *(__nv_bfloat162*)&hipack;
    __nv_bfloat162 p;
    p.x = __float2bfloat16(a - __bfloat162float(hp.x));
    p.y = __float2bfloat16(b - __bfloat162float(hp.y));
    return *(uint32_t*)&p;
}

// ---------------------------------------------------------------------------
// fp32 -> (hi, lo) bf16 split
// ---------------------------------------------------------------------------
__global__ __launch_bounds__(256)
void cvt_pair(const float* __restrict__ in, __nv_bfloat16* __restrict__ hi,
              __nv_bfloat16* __restrict__ lo, int n4)
{
    int i = blockIdx.x * blockDim.x + threadIdx.x;
    if (i >= n4) return;
    float4 v = ((const float4*)in)[i];
    ((uint32_t*)hi)[2*i]   = pack_bf16(v.x, v.y);
    ((uint32_t*)hi)[2*i+1] = pack_bf16(v.z, v.w);
    ((uint32_t*)lo)[2*i]   = pack_bf16_res(v.x, v.y, ((uint32_t*)hi)[2*i]);
    ((uint32_t*)lo)[2*i+1] = pack_bf16_res(v.z, v.w, ((uint32_t*)hi)[2*i+1]);
}

// ---------------------------------------------------------------------------
// HMMA GEMM: C[m,n] = sum_k A[m,k]*B[n,k], split bf16 (3 MMA passes), fp32 acc.
// K=1024. CTA 128x128, BK=32, 8 warps (2m x 4n). mode 0: split-bf16 scatter to
// g_qkvh/l (Q scaled). mode 1: +bias -> Cout fp32.
// ---------------------------------------------------------------------------
#define PK 40
#define MATB (128 * PK * 2)
#define BUFB (4 * MATB)
#define GSMEM (2 * BUFB)
#define NCHUNK 32

__global__ __launch_bounds__(256)
void hmma_gemm(const __nv_bfloat16* __restrict__ Ah, const __nv_bfloat16* __restrict__ Al,
               const __nv_bfloat16* __restrict__ Bh, const __nv_bfloat16* __restrict__ Bl,
               const float* __restrict__ bias, float* __restrict__ Cout, int mode)
{
    extern __shared__ char smem[];
    const uint32_t sb = smem_u32(smem);
    const int tid  = threadIdx.x;
    const int wid  = tid >> 5, lane = tid & 31;
    const int wm   = wid >> 2, wn = wid & 3;
    const int rowBase = blockIdx.y * 128;
    const int colBase = blockIdx.x * 128;

    const __nv_bfloat16* gp[4] = {Ah, Al, Bh, Bl};

    auto load_chunk = [&](int ci, int buf) {
        const int k0 = ci * 32;
        #pragma unroll
        for (int a = 0; a < 4; a++) {
            const __nv_bfloat16* src = gp[a];
            const int gRow = (a < 2) ? rowBase : colBase;
            const uint32_t mbase = sb + buf * BUFB + a * MATB;
            #pragma unroll
            for (int it = 0; it < 2; it++) {
                int idx = it * 256 + tid;
                int row = idx >> 2, seg = idx & 3;
                cp16(mbase + (uint32_t)(row * PK + seg * 8) * 2,
                     src + (size_t)(gRow + row) * 1024 + k0 + seg * 8);
            }
        }
        CP_COMMIT();
    };

    float acc[4][4][4];
    #pragma unroll
    for (int mi = 0; mi < 4; mi++)
        #pragma unroll
        for (int ni = 0; ni < 4; ni++)
            #pragma unroll
            for (int j = 0; j < 4; j++) acc[mi][ni][j] = 0.f;

    load_chunk(0, 0);

    for (int ci = 0; ci < NCHUNK; ci++) {
        const int buf = ci & 1;
        if (ci + 1 < NCHUNK) { load_chunk(ci + 1, buf ^ 1); CP_WAIT1(); }
        else                 { CP_WAIT0(); }
        __syncthreads();

        const uint32_t aBase = sb + buf * BUFB;
        const uint32_t bBase = sb + buf * BUFB + 2 * MATB;

        #pragma unroll
        for (int ks = 0; ks < 2; ks++) {
            uint32_t ah[4][4], al[4][4], bh[4][2], bl[4][2];
            const int acol = ks * 16 + (lane >> 4) * 8;
            const int bcol = ks * 16 + ((lane >> 3) & 1) * 8;
            #pragma unroll
            for (int mi = 0; mi < 4; mi++) {
                int r = wm * 64 + mi * 16 + (lane & 15);
                ldsm_x4(ah[mi], aBase + (uint32_t)(r * PK + acol) * 2);
                ldsm_x4(al[mi], aBase + MATB + (uint32_t)(r * PK + acol) * 2);
            }
            #pragma unroll
            for (int ni = 0; ni < 4; ni++) {
                int rn = wn * 32 + ni * 8 + (lane & 7);
                ldsm_x2(bh[ni], bBase + (uint32_t)(rn * PK + bcol) * 2);
                ldsm_x2(bl[ni], bBase + MATB + (uint32_t)(rn * PK + bcol) * 2);
            }
            #pragma unroll
            for (int mi = 0; mi < 4; mi++)
                #pragma unroll
                for (int ni = 0; ni < 4; ni++) {
                    mma_bf16(acc[mi][ni], ah[mi], bh[ni]);
                    mma_bf16(acc[mi][ni], ah[mi], bl[ni]);
                    mma_bf16(acc[mi][ni], al[mi], bh[ni]);
                }
        }
        __syncthreads();
    }

    const int rBase = rowBase + wm * 64 + (lane >> 2);
    const int cBase = colBase + wn * 32 + (lane & 3) * 2;
    #pragma unroll
    for (int mi = 0; mi < 4; mi++) {
        #pragma unroll
        for (int half = 0; half < 2; half++) {
            const int m = rBase + mi * 16 + half * 8;
            #pragma unroll
            for (int ni = 0; ni < 4; ni++) {
                const int n = cBase + ni * 8;
                float c0 = acc[mi][ni][half * 2 + 0];
                float c1 = acc[mi][ni][half * 2 + 1];
                if (mode == 0) {
                    int t = n >> 10, rem = n & 1023, h = rem >> 6, hd = rem & 63;
                    int b = m >> 9, nn = m & 511;
                    float s = (t == 0) ? 0.125f : 1.0f;
                    c0 *= s; c1 *= s;
                    size_t idx = ((((size_t)t * 32 + b) * 16 + h) * 512 + nn) * 64 + hd;
                    uint32_t hp = pack_bf16(c0, c1);
                    *(uint32_t*)(g_qkvh + idx) = hp;
                    *(uint32_t*)(g_qkvl + idx) = pack_bf16_res(c0, c1, hp);
                } else {
                    float* dst = Cout + (size_t)m * 1024 + n;
                    *(float2*)dst = make_float2(c0 + bias[n], c1 + bias[n + 1]);
                }
            }
        }
    }
}

// ---------------------------------------------------------------------------
// HMMA flash attention. CTA: 128 q rows, 8 warps x 16 rows, KV tiles of 64,
// double-buffered cp.async. 3-pass split-bf16 on both S=QK^T and O+=PV.
// Only the column mask bias matters (row bias cancels in softmax).
// ---------------------------------------------------------------------------
#define PKV 72
#define KVMAT (64 * PKV * 2)          // 9216 B
#define KVBUF (4 * KVMAT)             // 36864 B
#define ASMEM (2 * KVBUF + 512)       // + 2x 256B mask slots

__global__ __launch_bounds__(256)
void attn_hmma(const float* __restrict__ mask)
{
    extern __shared__ char smem[];
    const uint32_t sb = smem_u32(smem);
    const int b = blockIdx.z, h = blockIdx.y;
    const int tid = threadIdx.x;
    const int wid = tid >> 5, lane = tid & 31;

    const size_t hd_stride = (size_t)512 * 64;
    const size_t base_bh = ((size_t)b * 16 + h) * hd_stride;
    const __nv_bfloat16* Qh_g = g_qkvh + base_bh;
    const __nv_bfloat16* Ql_g = g_qkvl + base_bh;
    const __nv_bfloat16* Kh_g = g_qkvh + 32 * 16 * hd_stride + base_bh;
    const __nv_bfloat16* Kl_g = g_qkvl + 32 * 16 * hd_stride + base_bh;
    const __nv_bfloat16* Vh_g = g_qkvh + 2 * 32 * 16 * hd_stride + base_bh;
    const __nv_bfloat16* Vl_g = g_qkvl + 2 * 32 * 16 * hd_stride + base_bh;

    // Load Q fragments (row-major A operand, k = hd)
    const int r0 = blockIdx.x * 128 + wid * 16 + (lane >> 2);
    uint32_t qh[4][4], ql[4][4];
    #pragma unroll
    for (int ks = 0; ks < 4; ks++) {
        const int c0 = ks * 16 + 2 * (lane & 3);
        qh[ks][0] = *(const uint32_t*)(Qh_g + (size_t)r0 * 64 + c0);
        qh[ks][1] = *(const uint32_t*)(Qh_g + (size_t)(r0 + 8) * 64 + c0);
        qh[ks][2] = *(const uint32_t*)(Qh_g + (size_t)r0 * 64 + c0 + 8);
        qh[ks][3] = *(const uint32_t*)(Qh_g + (size_t)(r0 + 8) * 64 + c0 + 8);
        ql[ks][0] = *(const uint32_t*)(Ql_g + (size_t)r0 * 64 + c0);
        ql[ks][1] = *(const uint32_t*)(Ql_g + (size_t)(r0 + 8) * 64 + c0);
        ql[ks][2] = *(const uint32_t*)(Ql_g + (size_t)r0 * 64 + c0 + 8);
        ql[ks][3] = *(const uint32_t*)(Ql_g + (size_t)(r0 + 8) * 64 + c0 + 8);
    }

    float acc_o[8][4];
    #pragma unroll
    for (int ni = 0; ni < 8; ni++)
        #pragma unroll
        for (int j = 0; j < 4; j++) acc_o[ni][j] = 0.f;
    float m0 = -1e30f, m1 = -1e30f, l0 = 0.f, l1 = 0.f;

    const __nv_bfloat16* srcs[4] = {Kh_g, Kl_g, Vh_g, Vl_g};
    auto load_tile = [&](int kt, int buf) {
        #pragma unroll
        for (int mm = 0; mm < 4; mm++) {
            const uint32_t mbase = sb + buf * KVBUF + mm * KVMAT;
            #pragma unroll
            for (int it = 0; it < 2; it++) {
                int idx = it * 256 + tid;
                int row = idx >> 3, seg = idx & 7;
                cp16(mbase + (uint32_t)(row * PKV + seg * 8) * 2,
                     srcs[mm] + (size_t)(kt + row) * 64 + seg * 8);
            }
        }
        if (tid < 16) {
            float4 mv = *(const float4*)(mask + b * 512 + kt + tid * 4);
            *(float4*)(smem + 2 * KVBUF + buf * 256 + tid * 16) = mv;
        }
        CP_COMMIT();
    };

    load_tile(0, 0);

    for (int t = 0; t < 8; t++) {
        const int buf = t & 1;
        if (t < 7) { load_tile((t + 1) * 64, buf ^ 1); CP_WAIT1(); }
        else       { CP_WAIT0(); }
        __syncthreads();

        const uint32_t kb_h = sb + buf * KVBUF;
        const uint32_t vb_h = kb_h + 2 * KVMAT;
        const float* Msm = (const float*)(smem + 2 * KVBUF + buf * 256);

        // ---- S = Qh*Kh + Qh*Kl + Ql*Kh ----
        float s[8][4];
        #pragma unroll
        for (int ni = 0; ni < 8; ni++)
            #pragma unroll
            for (int j = 0; j < 4; j++) s[ni][j] = 0.f;

        const int g = lane >> 3;
        #pragma unroll
        for (int ks = 0; ks < 4; ks++) {
            uint32_t kh[8][2], kl[8][2];
            #pragma unroll
            for (int np = 0; np < 4; np++) {
                uint32_t a = kb_h +
                    (uint32_t)(((2 * np + (g >> 1)) * 8 + (lane & 7)) * PKV +
                               ks * 16 + (g & 1) * 8) * 2;
                ldsm_x4(&kh[2 * np][0], a);
                ldsm_x4(&kl[2 * np][0], a + KVMAT);
            }
            #pragma unroll
            for (int ni = 0; ni < 8; ni++) {
                mma_bf16(s[ni], qh[ks], kh[ni]);
                mma_bf16(s[ni], qh[ks], kl[ni]);
                mma_bf16(s[ni], ql[ks], kh[ni]);
            }
        }

        // ---- mask + online softmax ----
        float tmax0 = -1e30f, tmax1 = -1e30f;
        #pragma unroll
        for (int ni = 0; ni < 8; ni++) {
            float2 mv = *(const float2*)(Msm + ni * 8 + 2 * (lane & 3));
            s[ni][0] += mv.x; s[ni][1] += mv.y;
            s[ni][2] += mv.x; s[ni][3] += mv.y;
            tmax0 = fmaxf(tmax0, fmaxf(s[ni][0], s[ni][1]));
            tmax1 = fmaxf(tmax1, fmaxf(s[ni][2], s[ni][3]));
        }
        tmax0 = fmaxf(tmax0, __shfl_xor_sync(0xffffffffu, tmax0, 1));
        tmax0 = fmaxf(tmax0, __shfl_xor_sync(0xffffffffu, tmax0, 2));
        tmax1 = fmaxf(tmax1, __shfl_xor_sync(0xffffffffu, tmax1, 1));
        tmax1 = fmaxf(tmax1, __shfl_xor_sync(0xffffffffu, tmax1, 2));

        const float mn0 = fmaxf(m0, tmax0), mn1 = fmaxf(m1, tmax1);
        const float al0 = __expf(m0 - mn0), al1 = __expf(m1 - mn1);
        m0 = mn0; m1 = mn1;
        l0 *= al0; l1 *= al1;
        #pragma unroll
        for (int ni = 0; ni < 8; ni++) {
            acc_o[ni][0] *= al0; acc_o[ni][1] *= al0;
            acc_o[ni][2] *= al1; acc_o[ni][3] *= al1;
        }

        // ---- P = exp(S - m); split to bf16 A-fragments ----
        uint32_t pah[4][4], pal[4][4];
        #pragma unroll
        for (int ni = 0; ni < 8; ni++) {
            float p0 = __expf(s[ni][0] - mn0);
            float p1 = __expf(s[ni][1] - mn0);
            float p2 = __expf(s[ni][2] - mn1);
            float p3 = __expf(s[ni][3] - mn1);
            l0 += p0 + p1; l1 += p2 + p3;
            const int ks = ni >> 1, half = ni & 1;
            uint32_t h01 = pack_bf16(p0, p1);
            uint32_t h23 = pack_bf16(p2, p3);
            pah[ks][half * 2 + 0] = h01;
            pah[ks][half * 2 + 1] = h23;
            pal[ks][half * 2 + 0] = pack_bf16_res(p0, p1, h01);
            pal[ks][half * 2 + 1] = pack_bf16_res(p2, p3, h23);
        }

        // ---- O += Ph*Vh + Ph*Vl + Pl*Vh ----
        #pragma unroll
        for (int ks = 0; ks < 4; ks++) {
            uint32_t vh[8][2], vl[8][2];
            #pragma unroll
            for (int np = 0; np < 4; np++) {
                uint32_t a = vb_h +
                    (uint32_t)((ks * 16 + (g & 1) * 8 + (lane & 7)) * PKV +
                               (2 * np + (g >> 1)) * 8) * 2;
                ldsm_x4_t(&vh[2 * np][0], a);
                ldsm_x4_t(&vl[2 * np][0], a + KVMAT);
            }
            #pragma unroll
            for (int ni = 0; ni < 8; ni++) {
                mma_bf16(acc_o[ni], pah[ks], vh[ni]);
                mma_bf16(acc_o[ni], pah[ks], vl[ni]);
                mma_bf16(acc_o[ni], pal[ks], vh[ni]);
            }
        }
        __syncthreads();
    }

    // ---- finalize: reduce l over quad, normalize, write split bf16 ----
    l0 += __shfl_xor_sync(0xffffffffu, l0, 1);
    l0 += __shfl_xor_sync(0xffffffffu, l0, 2);
    l1 += __shfl_xor_sync(0xffffffffu, l1, 1);
    l1 += __shfl_xor_sync(0xffffffffu, l1, 2);
    const float inv0 = 1.0f / l0, inv1 = 1.0f / l1;

    const size_t rowA = ((size_t)b * 512 + r0) * 1024 + h * 64;
    const size_t rowB = ((size_t)b * 512 + r0 + 8) * 1024 + h * 64;
    #pragma unroll
    for (int ni = 0; ni < 8; ni++) {
        const int hd = ni * 8 + 2 * (lane & 3);
        float a0 = acc_o[ni][0] * inv0, a1 = acc_o[ni][1] * inv0;
        float a2 = acc_o[ni][2] * inv1, a3 = acc_o[ni][3] * inv1;
        uint32_t h01 = pack_bf16(a0, a1);
        uint32_t h23 = pack_bf16(a2, a3);
        *(uint32_t*)(g_aoh + rowA + hd) = h01;
        *(uint32_t*)(g_aol + rowA + hd) = pack_bf16_res(a0, a1, h01);
        *(uint32_t*)(g_aoh + rowB + hd) = h23;
        *(uint32_t*)(g_aol + rowB + hd) = pack_bf16_res(a2, a3, h23);
    }
}

// ---------------------------------------------------------------------------
extern "C" void kernel_launch(void* const* d_in, const int* in_sizes, int n_in,
                              void* d_out, int out_size)
{
    const float* x = nullptr;
    const float* mask = nullptr;
    const float* wqkv = nullptr;
    const float* wproj = nullptr;
    const float* bproj = nullptr;

    for (int i = 0; i < n_in; i++) {
        switch (in_sizes[i]) {
            case 32 * 512 * 1024:  x     = (const float*)d_in[i]; break;
            case 32 * 512:         mask  = (const float*)d_in[i]; break;
            case 3 * 1024 * 1024:  wqkv  = (const float*)d_in[i]; break;
            case 1024 * 1024:      wproj = (const float*)d_in[i]; break;
            case 1024:             bproj = (const float*)d_in[i]; break;
            default: break;
        }
    }

    static bool attr_set = false;
    if (!attr_set) {
        cudaFuncSetAttribute(hmma_gemm, cudaFuncAttributeMaxDynamicSharedMemorySize, GSMEM);
        cudaFuncSetAttribute(attn_hmma, cudaFuncAttributeMaxDynamicSharedMemorySize, ASMEM);
        attr_set = true;
    }

    __nv_bfloat16 *xh, *xl, *wqh, *wql, *wph, *wpl, *aoh, *aol;
    cudaGetSymbolAddress((void**)&xh,  g_xh);
    cudaGetSymbolAddress((void**)&xl,  g_xl);
    cudaGetSymbolAddress((void**)&wqh, g_wqh);
    cudaGetSymbolAddress((void**)&wql, g_wql);
    cudaGetSymbolAddress((void**)&wph, g_wph);
    cudaGetSymbolAddress((void**)&wpl, g_wpl);
    cudaGetSymbolAddress((void**)&aoh, g_aoh);
    cudaGetSymbolAddress((void**)&aol, g_aol);

    // split fp32 -> (hi, lo) bf16
    cvt_pair<<<(4194304 + 255) / 256, 256>>>(x,     xh,  xl,  4194304);
    cvt_pair<<<(786432  + 255) / 256, 256>>>(wqkv,  wqh, wql, 786432);
    cvt_pair<<<(262144  + 255) / 256, 256>>>(wproj, wph, wpl, 262144);

    // QKV projection -> split-bf16 g_qkvh/l (HMMA)
    hmma_gemm<<<dim3(24, 128), 256, GSMEM>>>(xh, xl, wqh, wql, nullptr, nullptr, 0);
    // HMMA flash attention -> g_aoh/g_aol
    attn_hmma<<<dim3(4, 16, 32), 256, ASMEM>>>(mask);
    // Output projection + bias -> d_out (HMMA)
    hmma_gemm<<<dim3(8, 128), 256, GSMEM>>>(aoh, aol, wph, wpl, bproj, (float*)d_out, 1);
}

// round 6
// speedup vs baseline: 3.0067x; 1.0242x over previous
#include <cuda_runtime.h>
#include <cuda_bf16.h>
#include <cstdint>

// ===========================================================================
// Problem constants: B=32, N=512, C=1024, H=16, HD=64, SCALE=0.125
// compute_103 toolchain: no tcgen05; tensor cores via mma.sync (HMMA).
// ===========================================================================

// split-bf16 qkv [3][B][H][N][HD] (Q pre-scaled by 0.125)
__device__ __nv_bfloat16 g_qkvh[3ull * 32 * 16 * 512 * 64];
__device__ __nv_bfloat16 g_qkvl[3ull * 32 * 16 * 512 * 64];
// split-bf16 inputs
__device__ __nv_bfloat16 g_xh[16777216], g_xl[16777216];      // x  [16384,1024]
__device__ __nv_bfloat16 g_wqh[3145728],  g_wql[3145728];     // W_qkv [3072,1024]
__device__ __nv_bfloat16 g_wph[1048576],  g_wpl[1048576];     // W_proj [1024,1024]
__device__ __nv_bfloat16 g_aoh[16777216], g_aol[16777216];    // attn out [B,N,C]

// ---------------------------------------------------------------------------
// PTX helpers (plain sm_80+ PTX — safe under compute_103)
// ---------------------------------------------------------------------------
__device__ __forceinline__ uint32_t smem_u32(const void* p) {
    uint32_t a;
    asm("{ .reg .u64 t; cvta.to.shared.u64 t, %1; cvt.u32.u64 %0, t; }" : "=r"(a) : "l"(p));
    return a;
}
__device__ __forceinline__ void mma_bf16(float* c, const uint32_t* a, const uint32_t* b) {
    asm volatile(
        "mma.sync.aligned.m16n8k16.row.col.f32.bf16.bf16.f32 "
        "{%0,%1,%2,%3}, {%4,%5,%6,%7}, {%8,%9}, {%0,%1,%2,%3};"
        : "+f"(c[0]), "+f"(c[1]), "+f"(c[2]), "+f"(c[3])
        : "r"(a[0]), "r"(a[1]), "r"(a[2]), "r"(a[3]), "r"(b[0]), "r"(b[1]));
}
__device__ __forceinline__ void ldsm_x4(uint32_t* r, uint32_t addr) {
    asm volatile("ldmatrix.sync.aligned.m8n8.x4.shared.b16 {%0,%1,%2,%3}, [%4];"
        : "=r"(r[0]), "=r"(r[1]), "=r"(r[2]), "=r"(r[3]) : "r"(addr));
}
__device__ __forceinline__ void ldsm_x4_b(uint32_t* r0, uint32_t* r1, uint32_t addr) {
    asm volatile("ldmatrix.sync.aligned.m8n8.x4.shared.b16 {%0,%1,%2,%3}, [%4];"
        : "=r"(r0[0]), "=r"(r0[1]), "=r"(r1[0]), "=r"(r1[1]) : "r"(addr));
}
__device__ __forceinline__ void ldsm_x4_t(uint32_t* r, uint32_t addr) {
    asm volatile("ldmatrix.sync.aligned.m8n8.x4.trans.shared.b16 {%0,%1,%2,%3}, [%4];"
        : "=r"(r[0]), "=r"(r[1]), "=r"(r[2]), "=r"(r[3]) : "r"(addr));
}
__device__ __forceinline__ void ldsm_x2(uint32_t* r, uint32_t addr) {
    asm volatile("ldmatrix.sync.aligned.m8n8.x2.shared.b16 {%0,%1}, [%2];"
        : "=r"(r[0]), "=r"(r[1]) : "r"(addr));
}
__device__ __forceinline__ void cp16(uint32_t saddr, const void* g) {
    asm volatile("cp.async.cg.shared.global [%0], [%1], 16;" :: "r"(saddr), "l"(g));
}
#define CP_COMMIT() asm volatile("cp.async.commit_group;" ::: "memory")
#define CP_WAIT1()  asm volatile("cp.async.wait_group 1;" ::: "memory")
#define CP_WAIT0()  asm volatile("cp.async.wait_group 0;" ::: "memory")

__device__ __forceinline__ uint32_t pack_bf16(float a, float b) {
    __nv_bfloat162 p;
    p.x = __float2bfloat16(a); p.y = __float2bfloat16(b);
    return *(uint32_t*)&p;
}
__device__ __forceinline__ uint32_t pack_bf16_res(float a, float b, uint32_t hipack) {
    __nv_bfloat162 hp = *(__nv_bfloat162*)&hipack;
    __nv_bfloat162 p;
    p.x = __float2bfloat16(a - __bfloat162float(hp.x));
    p.y = __float2bfloat16(b - __bfloat162float(hp.y));
    return *(uint32_t*)&p;
}

// ---------------------------------------------------------------------------
// fp32 -> (hi, lo) bf16 split
// ---------------------------------------------------------------------------
__global__ __launch_bounds__(256)
void cvt_pair(const float* __restrict__ in, __nv_bfloat16* __restrict__ hi,
              __nv_bfloat16* __restrict__ lo, int n4)
{
    int i = blockIdx.x * blockDim.x + threadIdx.x;
    if (i >= n4) return;
    float4 v = ((const float4*)in)[i];
    ((uint32_t*)hi)[2*i]   = pack_bf16(v.x, v.y);
    ((uint32_t*)hi)[2*i+1] = pack_bf16(v.z, v.w);
    ((uint32_t*)lo)[2*i]   = pack_bf16_res(v.x, v.y, ((uint32_t*)hi)[2*i]);
    ((uint32_t*)lo)[2*i+1] = pack_bf16_res(v.z, v.w, ((uint32_t*)hi)[2*i+1]);
}

// ---------------------------------------------------------------------------
// HMMA GEMM: C[m,n] = sum_k A[m,k]*B[n,k], split bf16 (3 MMA passes), fp32 acc.
// K=1024. CTA 128x128, BK=32, 4 warps (2m x 2n), 64x64 per warp.
// mode 0: split-bf16 scatter to g_qkvh/l (Q scaled). mode 1: +bias -> Cout.
// ---------------------------------------------------------------------------
#define PK 40
#define MATB (128 * PK * 2)
#define BUFB (4 * MATB)
#define GSMEM (2 * BUFB)
#define NCHUNK 32

__global__ __launch_bounds__(128)
void hmma_gemm(const __nv_bfloat16* __restrict__ Ah, const __nv_bfloat16* __restrict__ Al,
               const __nv_bfloat16* __restrict__ Bh, const __nv_bfloat16* __restrict__ Bl,
               const float* __restrict__ bias, float* __restrict__ Cout, int mode)
{
    extern __shared__ char smem[];
    const uint32_t sb = smem_u32(smem);
    const int tid  = threadIdx.x;
    const int wid  = tid >> 5, lane = tid & 31;
    const int wm   = wid >> 1, wn = wid & 1;          // 2 x 2 warp grid, 64x64/warp
    const int rowBase = blockIdx.y * 128;
    const int colBase = blockIdx.x * 128;

    const __nv_bfloat16* gp[4] = {Ah, Al, Bh, Bl};

    auto load_chunk = [&](int ci, int buf) {
        const int k0 = ci * 32;
        #pragma unroll
        for (int a = 0; a < 4; a++) {
            const __nv_bfloat16* src = gp[a];
            const int gRow = (a < 2) ? rowBase : colBase;
            const uint32_t mbase = sb + buf * BUFB + a * MATB;
            #pragma unroll
            for (int it = 0; it < 4; it++) {
                int idx = it * 128 + tid;        // 0..511
                int row = idx >> 2, seg = idx & 3;
                cp16(mbase + (uint32_t)(row * PK + seg * 8) * 2,
                     src + (size_t)(gRow + row) * 1024 + k0 + seg * 8);
            }
        }
        CP_COMMIT();
    };

    float acc[4][8][4];
    #pragma unroll
    for (int mi = 0; mi < 4; mi++)
        #pragma unroll
        for (int ni = 0; ni < 8; ni++)
            #pragma unroll
            for (int j = 0; j < 4; j++) acc[mi][ni][j] = 0.f;

    load_chunk(0, 0);

    for (int ci = 0; ci < NCHUNK; ci++) {
        const int buf = ci & 1;
        if (ci + 1 < NCHUNK) { load_chunk(ci + 1, buf ^ 1); CP_WAIT1(); }
        else                 { CP_WAIT0(); }
        __syncthreads();

        const uint32_t aBase = sb + buf * BUFB;
        const uint32_t bBase = sb + buf * BUFB + 2 * MATB;

        #pragma unroll
        for (int ks = 0; ks < 2; ks++) {
            uint32_t ah[4][4], al[4][4], bh[8][2], bl[8][2];
            const int acol = ks * 16 + (lane >> 4) * 8;
            #pragma unroll
            for (int mi = 0; mi < 4; mi++) {
                int r = wm * 64 + mi * 16 + (lane & 15);
                ldsm_x4(ah[mi], aBase + (uint32_t)(r * PK + acol) * 2);
                ldsm_x4(al[mi], aBase + MATB + (uint32_t)(r * PK + acol) * 2);
            }
            const int bcol = ks * 16 + ((lane >> 3) & 1) * 8;
            #pragma unroll
            for (int np = 0; np < 4; np++) {
                int nr = wn * 64 + np * 16 + ((lane >> 4) & 1) * 8 + (lane & 7);
                uint32_t a = bBase + (uint32_t)(nr * PK + bcol) * 2;
                ldsm_x4_b(bh[2 * np], bh[2 * np + 1], a);
                ldsm_x4_b(bl[2 * np], bl[2 * np + 1], a + MATB);
            }
            // pass 1: Ah*Bh
            #pragma unroll
            for (int mi = 0; mi < 4; mi++)
                #pragma unroll
                for (int ni = 0; ni < 8; ni++)
                    mma_bf16(acc[mi][ni], ah[mi], bh[ni]);
            // pass 2: Ah*Bl
            #pragma unroll
            for (int mi = 0; mi < 4; mi++)
                #pragma unroll
                for (int ni = 0; ni < 8; ni++)
                    mma_bf16(acc[mi][ni], ah[mi], bl[ni]);
            // pass 3: Al*Bh
            #pragma unroll
            for (int mi = 0; mi < 4; mi++)
                #pragma unroll
                for (int ni = 0; ni < 8; ni++)
                    mma_bf16(acc[mi][ni], al[mi], bh[ni]);
        }
        __syncthreads();
    }

    const int rBase = rowBase + wm * 64 + (lane >> 2);
    const int cBase = colBase + wn * 64 + (lane & 3) * 2;
    #pragma unroll
    for (int mi = 0; mi < 4; mi++) {
        #pragma unroll
        for (int half = 0; half < 2; half++) {
            const int m = rBase + mi * 16 + half * 8;
            #pragma unroll
            for (int ni = 0; ni < 8; ni++) {
                const int n = cBase + ni * 8;
                float c0 = acc[mi][ni][half * 2 + 0];
                float c1 = acc[mi][ni][half * 2 + 1];
                if (mode == 0) {
                    int t = n >> 10, rem = n & 1023, h = rem >> 6, hd = rem & 63;
                    int b = m >> 9, nn = m & 511;
                    float s = (t == 0) ? 0.125f : 1.0f;
                    c0 *= s; c1 *= s;
                    size_t idx = ((((size_t)t * 32 + b) * 16 + h) * 512 + nn) * 64 + hd;
                    uint32_t hp = pack_bf16(c0, c1);
                    *(uint32_t*)(g_qkvh + idx) = hp;
                    *(uint32_t*)(g_qkvl + idx) = pack_bf16_res(c0, c1, hp);
                } else {
                    float* dst = Cout + (size_t)m * 1024 + n;
                    *(float2*)dst = make_float2(c0 + bias[n], c1 + bias[n + 1]);
                }
            }
        }
    }
}

// ---------------------------------------------------------------------------
// HMMA flash attention. CTA: 128 q rows, 8 warps x 16 rows, KV tiles of 64,
// double-buffered cp.async. 3-pass split-bf16 on both S=QK^T and O+=PV.
// Only the column mask bias matters (row bias cancels in softmax).
// ---------------------------------------------------------------------------
#define PKV 72
#define KVMAT (64 * PKV * 2)          // 9216 B
#define KVBUF (4 * KVMAT)             // 36864 B
#define ASMEM (2 * KVBUF + 512)       // + 2x 256B mask slots

__global__ __launch_bounds__(256)
void attn_hmma(const float* __restrict__ mask)
{
    extern __shared__ char smem[];
    const uint32_t sb = smem_u32(smem);
    const int b = blockIdx.z, h = blockIdx.y;
    const int tid = threadIdx.x;
    const int wid = tid >> 5, lane = tid & 31;

    const size_t hd_stride = (size_t)512 * 64;
    const size_t base_bh = ((size_t)b * 16 + h) * hd_stride;
    const __nv_bfloat16* Qh_g = g_qkvh + base_bh;
    const __nv_bfloat16* Ql_g = g_qkvl + base_bh;
    const __nv_bfloat16* Kh_g = g_qkvh + 32 * 16 * hd_stride + base_bh;
    const __nv_bfloat16* Kl_g = g_qkvl + 32 * 16 * hd_stride + base_bh;
    const __nv_bfloat16* Vh_g = g_qkvh + 2 * 32 * 16 * hd_stride + base_bh;
    const __nv_bfloat16* Vl_g = g_qkvl + 2 * 32 * 16 * hd_stride + base_bh;

    const int r0 = blockIdx.x * 128 + wid * 16 + (lane >> 2);
    uint32_t qh[4][4], ql[4][4];
    #pragma unroll
    for (int ks = 0; ks < 4; ks++) {
        const int c0 = ks * 16 + 2 * (lane & 3);
        qh[ks][0] = *(const uint32_t*)(Qh_g + (size_t)r0 * 64 + c0);
        qh[ks][1] = *(const uint32_t*)(Qh_g + (size_t)(r0 + 8) * 64 + c0);
        qh[ks][2] = *(const uint32_t*)(Qh_g + (size_t)r0 * 64 + c0 + 8);
        qh[ks][3] = *(const uint32_t*)(Qh_g + (size_t)(r0 + 8) * 64 + c0 + 8);
        ql[ks][0] = *(const uint32_t*)(Ql_g + (size_t)r0 * 64 + c0);
        ql[ks][1] = *(const uint32_t*)(Ql_g + (size_t)(r0 + 8) * 64 + c0);
        ql[ks][2] = *(const uint32_t*)(Ql_g + (size_t)r0 * 64 + c0 + 8);
        ql[ks][3] = *(const uint32_t*)(Ql_g + (size_t)(r0 + 8) * 64 + c0 + 8);
    }

    float acc_o[8][4];
    #pragma unroll
    for (int ni = 0; ni < 8; ni++)
        #pragma unroll
        for (int j = 0; j < 4; j++) acc_o[ni][j] = 0.f;
    float m0 = -1e30f, m1 = -1e30f, l0 = 0.f, l1 = 0.f;

    const __nv_bfloat16* srcs[4] = {Kh_g, Kl_g, Vh_g, Vl_g};
    auto load_tile = [&](int kt, int buf) {
        #pragma unroll
        for (int mm = 0; mm < 4; mm++) {
            const uint32_t mbase = sb + buf * KVBUF + mm * KVMAT;
            #pragma unroll
            for (int it = 0; it < 2; it++) {
                int idx = it * 256 + tid;
                int row = idx >> 3, seg = idx & 7;
                cp16(mbase + (uint32_t)(row * PKV + seg * 8) * 2,
                     srcs[mm] + (size_t)(kt + row) * 64 + seg * 8);
            }
        }
        if (tid < 16) {
            float4 mv = *(const float4*)(mask + b * 512 + kt + tid * 4);
            *(float4*)(smem + 2 * KVBUF + buf * 256 + tid * 16) = mv;
        }
        CP_COMMIT();
    };

    load_tile(0, 0);

    for (int t = 0; t < 8; t++) {
        const int buf = t & 1;
        if (t < 7) { load_tile((t + 1) * 64, buf ^ 1); CP_WAIT1(); }
        else       { CP_WAIT0(); }
        __syncthreads();

        const uint32_t kb_h = sb + buf * KVBUF;
        const uint32_t vb_h = kb_h + 2 * KVMAT;
        const float* Msm = (const float*)(smem + 2 * KVBUF + buf * 256);

        float s[8][4];
        #pragma unroll
        for (int ni = 0; ni < 8; ni++)
            #pragma unroll
            for (int j = 0; j < 4; j++) s[ni][j] = 0.f;

        const int g = lane >> 3;
        #pragma unroll
        for (int ks = 0; ks < 4; ks++) {
            uint32_t kh[8][2], kl[8][2];
            #pragma unroll
            for (int np = 0; np < 4; np++) {
                uint32_t a = kb_h +
                    (uint32_t)(((2 * np + (g >> 1)) * 8 + (lane & 7)) * PKV +
                               ks * 16 + (g & 1) * 8) * 2;
                ldsm_x4(&kh[2 * np][0], a);
                ldsm_x4(&kl[2 * np][0], a + KVMAT);
            }
            #pragma unroll
            for (int ni = 0; ni < 8; ni++) {
                mma_bf16(s[ni], qh[ks], kh[ni]);
                mma_bf16(s[ni], qh[ks], kl[ni]);
                mma_bf16(s[ni], ql[ks], kh[ni]);
            }
        }

        float tmax0 = -1e30f, tmax1 = -1e30f;
        #pragma unroll
        for (int ni = 0; ni < 8; ni++) {
            float2 mv = *(const float2*)(Msm + ni * 8 + 2 * (lane & 3));
            s[ni][0] += mv.x; s[ni][1] += mv.y;
            s[ni][2] += mv.x; s[ni][3] += mv.y;
            tmax0 = fmaxf(tmax0, fmaxf(s[ni][0], s[ni][1]));
            tmax1 = fmaxf(tmax1, fmaxf(s[ni][2], s[ni][3]));
        }
        tmax0 = fmaxf(tmax0, __shfl_xor_sync(0xffffffffu, tmax0, 1));
        tmax0 = fmaxf(tmax0, __shfl_xor_sync(0xffffffffu, tmax0, 2));
        tmax1 = fmaxf(tmax1, __shfl_xor_sync(0xffffffffu, tmax1, 1));
        tmax1 = fmaxf(tmax1, __shfl_xor_sync(0xffffffffu, tmax1, 2));

        const float mn0 = fmaxf(m0, tmax0), mn1 = fmaxf(m1, tmax1);
        const float al0 = __expf(m0 - mn0), al1 = __expf(m1 - mn1);
        m0 = mn0; m1 = mn1;
        l0 *= al0; l1 *= al1;
        #pragma unroll
        for (int ni = 0; ni < 8; ni++) {
            acc_o[ni][0] *= al0; acc_o[ni][1] *= al0;
            acc_o[ni][2] *= al1; acc_o[ni][3] *= al1;
        }

        uint32_t pah[4][4], pal[4][4];
        #pragma unroll
        for (int ni = 0; ni < 8; ni++) {
            float p0 = __expf(s[ni][0] - mn0);
            float p1 = __expf(s[ni][1] - mn0);
            float p2 = __expf(s[ni][2] - mn1);
            float p3 = __expf(s[ni][3] - mn1);
            l0 += p0 + p1; l1 += p2 + p3;
            const int ks = ni >> 1, half = ni & 1;
            uint32_t h01 = pack_bf16(p0, p1);
            uint32_t h23 = pack_bf16(p2, p3);
            pah[ks][half * 2 + 0] = h01;
            pah[ks][half * 2 + 1] = h23;
            pal[ks][half * 2 + 0] = pack_bf16_res(p0, p1, h01);
            pal[ks][half * 2 + 1] = pack_bf16_res(p2, p3, h23);
        }

        #pragma unroll
        for (int ks = 0; ks < 4; ks++) {
            uint32_t vh[8][2], vl[8][2];
            #pragma unroll
            for (int np = 0; np < 4; np++) {
                uint32_t a = vb_h +
                    (uint32_t)((ks * 16 + (g & 1) * 8 + (lane & 7)) * PKV +
                               (2 * np + (g >> 1)) * 8) * 2;
                ldsm_x4_t(&vh[2 * np][0], a);
                ldsm_x4_t(&vl[2 * np][0], a + KVMAT);
            }
            #pragma unroll
            for (int ni = 0; ni < 8; ni++) {
                mma_bf16(acc_o[ni], pah[ks], vh[ni]);
                mma_bf16(acc_o[ni], pah[ks], vl[ni]);
                mma_bf16(acc_o[ni], pal[ks], vh[ni]);
            }
        }
        __syncthreads();
    }

    l0 += __shfl_xor_sync(0xffffffffu, l0, 1);
    l0 += __shfl_xor_sync(0xffffffffu, l0, 2);
    l1 += __shfl_xor_sync(0xffffffffu, l1, 1);
    l1 += __shfl_xor_sync(0xffffffffu, l1, 2);
    const float inv0 = 1.0f / l0, inv1 = 1.0f / l1;

    const size_t rowA = ((size_t)b * 512 + r0) * 1024 + h * 64;
    const size_t rowB = ((size_t)b * 512 + r0 + 8) * 1024 + h * 64;
    #pragma unroll
    for (int ni = 0; ni < 8; ni++) {
        const int hd = ni * 8 + 2 * (lane & 3);
        float a0 = acc_o[ni][0] * inv0, a1 = acc_o[ni][1] * inv0;
        float a2 = acc_o[ni][2] * inv1, a3 = acc_o[ni][3] * inv1;
        uint32_t h01 = pack_bf16(a0, a1);
        uint32_t h23 = pack_bf16(a2, a3);
        *(uint32_t*)(g_aoh + rowA + hd) = h01;
        *(uint32_t*)(g_aol + rowA + hd) = pack_bf16_res(a0, a1, h01);
        *(uint32_t*)(g_aoh + rowB + hd) = h23;
        *(uint32_t*)(g_aol + rowB + hd) = pack_bf16_res(a2, a3, h23);
    }
}

// ---------------------------------------------------------------------------
extern "C" void kernel_launch(void* const* d_in, const int* in_sizes, int n_in,
                              void* d_out, int out_size)
{
    const float* x = nullptr;
    const float* mask = nullptr;
    const float* wqkv = nullptr;
    const float* wproj = nullptr;
    const float* bproj = nullptr;

    for (int i = 0; i < n_in; i++) {
        switch (in_sizes[i]) {
            case 32 * 512 * 1024:  x     = (const float*)d_in[i]; break;
            case 32 * 512:         mask  = (const float*)d_in[i]; break;
            case 3 * 1024 * 1024:  wqkv  = (const float*)d_in[i]; break;
            case 1024 * 1024:      wproj = (const float*)d_in[i]; break;
            case 1024:             bproj = (const float*)d_in[i]; break;
            default: break;
        }
    }

    static bool attr_set = false;
    if (!attr_set) {
        cudaFuncSetAttribute(hmma_gemm, cudaFuncAttributeMaxDynamicSharedMemorySize, GSMEM);
        cudaFuncSetAttribute(attn_hmma, cudaFuncAttributeMaxDynamicSharedMemorySize, ASMEM);
        attr_set = true;
    }

    __nv_bfloat16 *xh, *xl, *wqh, *wql, *wph, *wpl, *aoh, *aol;
    cudaGetSymbolAddress((void**)&xh,  g_xh);
    cudaGetSymbolAddress((void**)&xl,  g_xl);
    cudaGetSymbolAddress((void**)&wqh, g_wqh);
    cudaGetSymbolAddress((void**)&wql, g_wql);
    cudaGetSymbolAddress((void**)&wph, g_wph);
    cudaGetSymbolAddress((void**)&wpl, g_wpl);
    cudaGetSymbolAddress((void**)&aoh, g_aoh);
    cudaGetSymbolAddress((void**)&aol, g_aol);

    // split fp32 -> (hi, lo) bf16
    cvt_pair<<<(4194304 + 255) / 256, 256>>>(x,     xh,  xl,  4194304);
    cvt_pair<<<(786432  + 255) / 256, 256>>>(wqkv,  wqh, wql, 786432);
    cvt_pair<<<(262144  + 255) / 256, 256>>>(wproj, wph, wpl, 262144);

    // QKV projection -> split-bf16 g_qkvh/l (HMMA)
    hmma_gemm<<<dim3(24, 128), 128, GSMEM>>>(xh, xl, wqh, wql, nullptr, nullptr, 0);
    // HMMA flash attention -> g_aoh/g_aol
    attn_hmma<<<dim3(4, 16, 32), 256, ASMEM>>>(mask);
    // Output projection + bias -> d_out (HMMA)
    hmma_gemm<<<dim3(8, 128), 128, GSMEM>>>(aoh, aol, wph, wpl, bproj, (float*)d_out, 1);
}